// round 11
// baseline (speedup 1.0000x reference)
#include <cuda_runtime.h>
#include <math.h>

// RoI max pooling (Caffe-style), bit-matching the JAX/XLA reference.
//   x    : [B=2, C=128, H=64, W=64] fp32
//   rois : [N=256, 5]  (batch_idx, x1, y1, x2, y2) image coords
//   out  : [N, C, 7, 7] fp32
//
// R11: R10 (float4 gather, hoisted masks) is mixed issue/L1 bound.
// Cut issued instructions per output ~2x:
//  - bounds precomputed once per (roi,bin) into __device__ scratch
//  - each gather thread handles 2 channels (c, c+64): independent load
//    streams (2x MLP), all bin overhead amortized over 2 outputs
//  - interior q-blocks take a mask-free fast path
//
// CRITICAL (bit-exactness): XLA rewrites `roi / 7` into `roi * fl32(1/7)`.
// Must use the same reciprocal multiply or floor/ceil bin boundaries shift
// by 1 ulp on 7-divisible roi extents (caused rel_err 9.6e-2 in R1/R3).

#define B_  2
#define C_  128
#define H_  64
#define W_  64
#define S_  (H_ * W_)        // 4096
#define W4_ (W_ / 4)         // 16 float4 per row
#define N_  256
#define OUTH_ 7
#define OUTW_ 7
#define NB_  (OUTH_ * OUTW_) // 49
#define NBINS_ (N_ * NB_)    // 12544
#define SCALE_ (1.0f / 16.0f)
#define RCP7_  (1.0f / 7.0f) // fp32 RN: 0x3E124925

// scratch (static device globals -> no allocation)
__device__ int4 g_bounds[NBINS_];   // clamped {hs, he, ws, we}
__device__ int  g_bidx[N_];

// ------------------------------------------------------------------ bounds
__global__ void roi_bounds_kernel(const float* __restrict__ rois) {
    int tid = blockIdx.x * blockDim.x + threadIdx.x;
    if (tid >= NBINS_) return;

    const int k  = tid % NB_;
    const int n  = tid / NB_;
    const int pw = k % OUTW_;
    const int ph = k / OUTW_;

    const float* r = rois + n * 5;
    const int xs = (int)rintf(r[1] * SCALE_);
    const int ys = (int)rintf(r[2] * SCALE_);
    const int xe = (int)rintf(r[3] * SCALE_);
    const int ye = (int)rintf(r[4] * SCALE_);

    const float roi_w = (float)max(xe - xs + 1, 1);
    const float roi_h = (float)max(ye - ys + 1, 1);
    // match XLA's divide -> multiply-by-reciprocal rewrite exactly
    const float bin_h = __fmul_rn(roi_h, RCP7_);
    const float bin_w = __fmul_rn(roi_w, RCP7_);

    int hs = (int)floorf(__fmul_rn((float)ph, bin_h)) + ys;
    int he = (int)ceilf(__fmul_rn((float)ph + 1.0f, bin_h)) + ys;
    int ws = (int)floorf(__fmul_rn((float)pw, bin_w)) + xs;
    int we = (int)ceilf(__fmul_rn((float)pw + 1.0f, bin_w)) + xs;
    hs = min(max(hs, 0), H_);
    he = min(max(he, 0), H_);
    ws = min(max(ws, 0), W_);
    we = min(max(we, 0), W_);

    g_bounds[tid] = make_int4(hs, he, ws, we);
    if (k == 0) g_bidx[n] = (int)r[0];
}

// ------------------------------------------------------------------ gather
// One thread = one bin x two channels (c, c+64). 802816 threads.
__global__ void roi_pool_kernel(const float* __restrict__ x,
                                float* __restrict__ out) {
    const int total = N_ * (C_ / 2) * NB_;
    int idx = blockIdx.x * blockDim.x + threadIdx.x;
    if (idx >= total) return;

    const int bin = idx % NB_;
    const int t   = idx / NB_;
    const int c   = t & (C_ / 2 - 1);   // 0..63
    const int n   = t >> 6;

    const int4 b   = g_bounds[n * NB_ + bin];
    const int bidx = g_bidx[n];

    const bool empty = (b.y <= b.x) || (b.w <= b.z);

    float m0 = -INFINITY, m1 = -INFINITY;

    if (!empty) {
        const float4* p0 =
            (const float4*)(x + ((size_t)bidx * C_ + c) * S_);
        const float4* p1 = p0 + (size_t)(C_ / 2) * (S_ / 4);

        const int q0 = b.z >> 2;
        const int q1 = (b.w - 1) >> 2;   // inclusive
        for (int q = q0; q <= q1; ++q) {
            float4 a0 = make_float4(-INFINITY, -INFINITY, -INFINITY, -INFINITY);
            float4 a1 = a0;
            const float4* r0 = p0 + b.x * W4_ + q;
            const float4* r1 = p1 + b.x * W4_ + q;
            for (int h = b.x; h < b.y; ++h, r0 += W4_, r1 += W4_) {
                const float4 v0 = __ldg(r0);   // independent streams: MLP 2x
                const float4 v1 = __ldg(r1);
                a0.x = fmaxf(a0.x, v0.x); a0.y = fmaxf(a0.y, v0.y);
                a0.z = fmaxf(a0.z, v0.z); a0.w = fmaxf(a0.w, v0.w);
                a1.x = fmaxf(a1.x, v1.x); a1.y = fmaxf(a1.y, v1.y);
                a1.z = fmaxf(a1.z, v1.z); a1.w = fmaxf(a1.w, v1.w);
            }
            const int wb = q << 2;
            if (wb >= b.z && wb + 3 < b.w) {
                // interior q-block: mask-free merge
                m0 = fmaxf(m0, fmaxf(fmaxf(a0.x, a0.y), fmaxf(a0.z, a0.w)));
                m1 = fmaxf(m1, fmaxf(fmaxf(a1.x, a1.y), fmaxf(a1.z, a1.w)));
            } else {
                // boundary q-block: per-element window mask
                if (wb + 0 >= b.z && wb + 0 < b.w) { m0 = fmaxf(m0, a0.x); m1 = fmaxf(m1, a1.x); }
                if (wb + 1 >= b.z && wb + 1 < b.w) { m0 = fmaxf(m0, a0.y); m1 = fmaxf(m1, a1.y); }
                if (wb + 2 >= b.z && wb + 2 < b.w) { m0 = fmaxf(m0, a0.z); m1 = fmaxf(m1, a1.z); }
                if (wb + 3 >= b.z && wb + 3 < b.w) { m0 = fmaxf(m0, a0.w); m1 = fmaxf(m1, a1.w); }
            }
        }
    }

    const size_t o0 = ((size_t)n * C_ + c) * NB_ + bin;
    out[o0]                           = empty ? 0.0f : m0;
    out[o0 + (size_t)(C_ / 2) * NB_]  = empty ? 0.0f : m1;
}

extern "C" void kernel_launch(void* const* d_in, const int* in_sizes, int n_in,
                              void* d_out, int out_size) {
    const float* x    = (const float*)d_in[0];
    const float* rois = (const float*)d_in[1];
    float* out = (float*)d_out;

    const int threads = 256;
    roi_bounds_kernel<<<(NBINS_ + threads - 1) / threads, threads>>>(rois);

    const int total = N_ * (C_ / 2) * NB_;
    roi_pool_kernel<<<(total + threads - 1) / threads, threads>>>(x, out);
}

// round 13
// speedup vs baseline: 1.2416x; 1.2416x over previous
#include <cuda_runtime.h>
#include <math.h>

// RoI max pooling (Caffe-style), bit-matching the JAX/XLA reference.
//   x    : [B=2, C=128, H=64, W=64] fp32
//   rois : [N=256, 5]  (batch_idx, x1, y1, x2, y2) image coords
//   out  : [N, C, 7, 7] fp32
//
// R13 = R12 resubmitted (R12 hit a GPU-broker acquisition timeout; never ran).
// Channels-last, warp-per-bin. NCHW family pinned at ~22us by intra-warp
// divergence (each LDG.128 -> ~7-10 wavefronts). Here a warp owns ONE bin;
// lane = 4 consecutive channels (float4). Every window position is one
// LDG.128 covering 512B contiguous (zero wasted wavefronts), no window
// masks, 32-bit address math, 4 independent max chains per lane.
// Transpose + smem-staged writeback as in R7.
//
// CRITICAL (bit-exactness): XLA rewrites `roi / 7` into `roi * fl32(1/7)`.
// Must use the same reciprocal multiply or floor/ceil bin boundaries shift
// by 1 ulp on 7-divisible roi extents (caused rel_err 9.6e-2 in R1/R3).

#define B_  2
#define C_  128
#define H_  64
#define W_  64
#define S_  (H_ * W_)        // 4096
#define N_  256
#define OUTH_ 7
#define OUTW_ 7
#define NB_  (OUTH_ * OUTW_) // 49
#define SCALE_ (1.0f / 16.0f)
#define RCP7_  (1.0f / 7.0f) // fp32 RN: 0x3E124925
#define TSTRIDE_ 132         // smem tile row stride (floats), 16B-aligned, conflict-light

// channels-last scratch copy of x (static device global -> no allocation), 4 MB
__device__ float g_xt[B_ * S_ * C_];   // [b][h][w][c]

// ---------------------------------------------------------------- transpose
// x[b][c][s] -> xt[b][s][c], 32x32 smem tiles, coalesced both sides. (R6-proven)
__global__ void transpose_kernel(const float* __restrict__ x) {
    __shared__ float t[32][33];
    const int b  = blockIdx.z;
    const int s0 = blockIdx.x * 32;
    const int c0 = blockIdx.y * 32;
    #pragma unroll
    for (int i = 0; i < 4; ++i) {
        const int c = c0 + threadIdx.y + i * 8;
        t[threadIdx.y + i * 8][threadIdx.x] =
            x[((size_t)b * C_ + c) * S_ + s0 + threadIdx.x];
    }
    __syncthreads();
    #pragma unroll
    for (int i = 0; i < 4; ++i) {
        const int s = s0 + threadIdx.y + i * 8;
        g_xt[((size_t)b * S_ + s) * C_ + c0 + threadIdx.x] =
            t[threadIdx.x][threadIdx.y + i * 8];
    }
}

// --------------------------------------------------------------------- pool
// Block = (ph, n), 256 threads = 8 warps. Warp w < 7 owns bin pw = w.
// Lane = channels [4*lane, 4*lane+4) via float4: each window position is
// one LDG.128 per warp, 512B contiguous.
__global__ void roi_pool_kernel(const float* __restrict__ rois,
                                float* __restrict__ out) {
    __shared__ float tile[OUTW_ * TSTRIDE_];   // [pw][c]

    const int ph   = blockIdx.x;
    const int n    = blockIdx.y;
    const int t    = threadIdx.x;
    const int wid  = t >> 5;
    const int lane = t & 31;

    if (wid < OUTW_) {
        const int pw = wid;
        // uniform per-warp bounds (all lanes compute identically; no divergence)
        const float* r = rois + n * 5;
        const int bidx = (int)r[0];
        const int xs = (int)rintf(r[1] * SCALE_);
        const int ys = (int)rintf(r[2] * SCALE_);
        const int xe = (int)rintf(r[3] * SCALE_);
        const int ye = (int)rintf(r[4] * SCALE_);
        const float roi_w = (float)max(xe - xs + 1, 1);
        const float roi_h = (float)max(ye - ys + 1, 1);
        // match XLA's divide -> multiply-by-reciprocal rewrite exactly
        const float bin_h = __fmul_rn(roi_h, RCP7_);
        const float bin_w = __fmul_rn(roi_w, RCP7_);
        int hs = (int)floorf(__fmul_rn((float)ph, bin_h)) + ys;
        int he = (int)ceilf(__fmul_rn((float)ph + 1.0f, bin_h)) + ys;
        int ws = (int)floorf(__fmul_rn((float)pw, bin_w)) + xs;
        int we = (int)ceilf(__fmul_rn((float)pw + 1.0f, bin_w)) + xs;
        hs = min(max(hs, 0), H_);
        he = min(max(he, 0), H_);
        ws = min(max(ws, 0), W_);
        we = min(max(we, 0), W_);

        const bool empty = (he <= hs) || (we <= ws);

        float4 acc = make_float4(-INFINITY, -INFINITY, -INFINITY, -INFINITY);
        const int pbase = bidx * (S_ * C_);   // 32-bit offsets (4M floats total)
        for (int h = hs; h < he; ++h) {
            const float4* rowp =
                (const float4*)(g_xt + pbase + (h << 13)) + lane;  // h*W_*C_ = h<<13
            for (int w = ws; w < we; ++w) {
                const float4 v = __ldg(rowp + (w << 5));  // w*C_ floats = w*32 float4
                acc.x = fmaxf(acc.x, v.x);
                acc.y = fmaxf(acc.y, v.y);
                acc.z = fmaxf(acc.z, v.z);
                acc.w = fmaxf(acc.w, v.w);
            }
        }
        if (empty) acc = make_float4(0.0f, 0.0f, 0.0f, 0.0f);
        // stage: tile[pw][c], c = 4*lane..4*lane+3 (16B-aligned: TSTRIDE_*4 % 16 == 0)
        ((float4*)(tile + pw * TSTRIDE_))[lane] = acc;
    }
    __syncthreads();

    // writeback: out[n][c][ph*7 + pw], 7-float contiguous runs per channel
    float* outn = out + (size_t)n * (C_ * NB_) + ph * OUTW_;
    for (int o = t; o < C_ * OUTW_; o += 256) {
        const int c  = o / OUTW_;
        const int pw = o - c * OUTW_;
        outn[c * NB_ + pw] = tile[pw * TSTRIDE_ + c];
    }
}

extern "C" void kernel_launch(void* const* d_in, const int* in_sizes, int n_in,
                              void* d_out, int out_size) {
    const float* x    = (const float*)d_in[0];
    const float* rois = (const float*)d_in[1];
    float* out = (float*)d_out;

    transpose_kernel<<<dim3(S_ / 32, C_ / 32, B_), dim3(32, 8)>>>(x);
    roi_pool_kernel<<<dim3(OUTH_, N_), 256>>>(rois, out);
}

// round 15
// speedup vs baseline: 1.4186x; 1.1426x over previous
#include <cuda_runtime.h>
#include <math.h>

// RoI max pooling (Caffe-style), bit-matching the JAX/XLA reference.
//   x    : [B=2, C=128, H=64, W=64] fp32
//   rois : [N=256, 5]  (batch_idx, x1, y1, x2, y2) image coords
//   out  : [N, C, 7, 7] fp32
//
// R15 = R14 with the address-math bug fixed: base pointer is float4*, so
// the row stride is W*C/4 = 2048 float4 = (h << 11), NOT (h << 9). R14
// used the wrong shift -> rel_err 0.49.
//
// Design: channels-last, warp-per-bin, lane = 4 consecutive channels via
// float4. Gather runs a counted loop over window positions in chunks of 4:
// incremental (h,w) advance, 4 back-to-back independent LDG.128 (explicit
// MLP=4), one FMNMX tree. Past-end positions clamp to the last valid
// position -- duplicates are harmless under max, so no masks.
//
// CRITICAL (bit-exactness): XLA rewrites `roi / 7` into `roi * fl32(1/7)`.
// Must use the same reciprocal multiply or floor/ceil bin boundaries shift
// by 1 ulp on 7-divisible roi extents (caused rel_err 9.6e-2 in R1/R3).

#define B_  2
#define C_  128
#define H_  64
#define W_  64
#define S_  (H_ * W_)        // 4096
#define N_  256
#define OUTH_ 7
#define OUTW_ 7
#define NB_  (OUTH_ * OUTW_) // 49
#define SCALE_ (1.0f / 16.0f)
#define RCP7_  (1.0f / 7.0f) // fp32 RN: 0x3E124925
#define TSTRIDE_ 132         // smem tile row stride (floats), 16B-aligned

// channels-last scratch copy of x (static device global -> no allocation), 4 MB
__device__ float g_xt[B_ * S_ * C_];   // [b][h][w][c]

// ---------------------------------------------------------------- transpose
__global__ void transpose_kernel(const float* __restrict__ x) {
    __shared__ float t[32][33];
    const int b  = blockIdx.z;
    const int s0 = blockIdx.x * 32;
    const int c0 = blockIdx.y * 32;
    #pragma unroll
    for (int i = 0; i < 4; ++i) {
        const int c = c0 + threadIdx.y + i * 8;
        t[threadIdx.y + i * 8][threadIdx.x] =
            x[((size_t)b * C_ + c) * S_ + s0 + threadIdx.x];
    }
    __syncthreads();
    #pragma unroll
    for (int i = 0; i < 4; ++i) {
        const int s = s0 + threadIdx.y + i * 8;
        g_xt[((size_t)b * S_ + s) * C_ + c0 + threadIdx.x] =
            t[threadIdx.x][threadIdx.y + i * 8];
    }
}

// --------------------------------------------------------------------- pool
// Block = (ph, n), 256 threads = 8 warps. Warp w < 7 owns bin pw = w.
// Lane = channels [4*lane, 4*lane+4) via float4.
__global__ void roi_pool_kernel(const float* __restrict__ rois,
                                float* __restrict__ out) {
    __shared__ float tile[OUTW_ * TSTRIDE_];   // [pw][c]

    const int ph   = blockIdx.x;
    const int n    = blockIdx.y;
    const int t    = threadIdx.x;
    const int wid  = t >> 5;
    const int lane = t & 31;

    if (wid < OUTW_) {
        const int pw = wid;
        // uniform per-warp bounds (all lanes compute identically)
        const float* r = rois + n * 5;
        const int bidx = (int)r[0];
        const int xs = (int)rintf(r[1] * SCALE_);
        const int ys = (int)rintf(r[2] * SCALE_);
        const int xe = (int)rintf(r[3] * SCALE_);
        const int ye = (int)rintf(r[4] * SCALE_);
        const float roi_w = (float)max(xe - xs + 1, 1);
        const float roi_h = (float)max(ye - ys + 1, 1);
        // match XLA's divide -> multiply-by-reciprocal rewrite exactly
        const float bin_h = __fmul_rn(roi_h, RCP7_);
        const float bin_w = __fmul_rn(roi_w, RCP7_);
        int hs = (int)floorf(__fmul_rn((float)ph, bin_h)) + ys;
        int he = (int)ceilf(__fmul_rn((float)ph + 1.0f, bin_h)) + ys;
        int ws = (int)floorf(__fmul_rn((float)pw, bin_w)) + xs;
        int we = (int)ceilf(__fmul_rn((float)pw + 1.0f, bin_w)) + xs;
        hs = min(max(hs, 0), H_);
        he = min(max(he, 0), H_);
        ws = min(max(ws, 0), W_);
        we = min(max(we, 0), W_);

        const bool empty = (he <= hs) || (we <= ws);
        const int total = empty ? 0 : (he - hs) * (we - ws);

        float4 acc = make_float4(-INFINITY, -INFINITY, -INFINITY, -INFINITY);
        // base pointer in float4 units: offset(h,w) = h*2048 + w*32 (+lane)
        const float4* pB =
            (const float4*)(g_xt + bidx * (S_ * C_)) + lane;

        int h = hs, w = ws;
        for (int base = 0; base < total; base += 4) {
            // 4 addresses via incremental advance; past-end positions clamp
            // to the last valid (h,w) -> harmless duplicate under max
            int o0 = (h << 11) + (w << 5);
            ++w; if (w == we) { w = ws; h = (h + 1 < he) ? h + 1 : h; }
            int o1 = (h << 11) + (w << 5);
            ++w; if (w == we) { w = ws; h = (h + 1 < he) ? h + 1 : h; }
            int o2 = (h << 11) + (w << 5);
            ++w; if (w == we) { w = ws; h = (h + 1 < he) ? h + 1 : h; }
            int o3 = (h << 11) + (w << 5);
            ++w; if (w == we) { w = ws; h = (h + 1 < he) ? h + 1 : h; }

            // 4 independent loads in flight before any consumer
            const float4 v0 = __ldg(pB + o0);
            const float4 v1 = __ldg(pB + o1);
            const float4 v2 = __ldg(pB + o2);
            const float4 v3 = __ldg(pB + o3);

            // FMNMX tree (depth 3), short dependence on acc
            acc.x = fmaxf(acc.x, fmaxf(fmaxf(v0.x, v1.x), fmaxf(v2.x, v3.x)));
            acc.y = fmaxf(acc.y, fmaxf(fmaxf(v0.y, v1.y), fmaxf(v2.y, v3.y)));
            acc.z = fmaxf(acc.z, fmaxf(fmaxf(v0.z, v1.z), fmaxf(v2.z, v3.z)));
            acc.w = fmaxf(acc.w, fmaxf(fmaxf(v0.w, v1.w), fmaxf(v2.w, v3.w)));
        }

        if (empty) acc = make_float4(0.0f, 0.0f, 0.0f, 0.0f);
        ((float4*)(tile + pw * TSTRIDE_))[lane] = acc;
    }
    __syncthreads();

    // writeback: out[n][c][ph*7 + pw]
    float* outn = out + (size_t)n * (C_ * NB_) + ph * OUTW_;
    for (int o = t; o < C_ * OUTW_; o += 256) {
        const int c  = o / OUTW_;
        const int pw = o - c * OUTW_;
        outn[c * NB_ + pw] = tile[pw * TSTRIDE_ + c];
    }
}

extern "C" void kernel_launch(void* const* d_in, const int* in_sizes, int n_in,
                              void* d_out, int out_size) {
    const float* x    = (const float*)d_in[0];
    const float* rois = (const float*)d_in[1];
    float* out = (float*)d_out;

    transpose_kernel<<<dim3(S_ / 32, C_ / 32, B_), dim3(32, 8)>>>(x);
    roi_pool_kernel<<<dim3(OUTH_, N_), 256>>>(rois, out);
}